// round 1
// baseline (speedup 1.0000x reference)
#include <cuda_runtime.h>

// CombPool2d: out = (w_avg^2)*avg_pool2x2(x) + (w_max^2)*max_pool2x2(x)
// x: (16,192,224,224) fp32, w: (1,192,1,1) fp32, out: (16,192,112,112) fp32
// Non-overlapping 2x2 windows, stride 2 -> pure streaming, HBM-bound.

#define B   16
#define C   192
#define HI  224
#define WI  224
#define HO  112
#define WO  112
#define WP  (WO / 2)   // output-pixel pairs per row = 56

__global__ __launch_bounds__(256)
void comb_pool2d_kernel(const float* __restrict__ x,
                        const float* __restrict__ w_avg,
                        const float* __restrict__ w_max,
                        float* __restrict__ out)
{
    const int total = B * C * HO * WP;            // 19,267,584
    int tid = blockIdx.x * blockDim.x + threadIdx.x;
    if (tid >= total) return;

    int wp = tid % WP;          // which pair of output columns
    int t  = tid / WP;
    int h  = t % HO;            // output row
    int bc = t / HO;            // fused batch*channel index
    int c  = bc % C;

    // Input base for this thread's 2x4 patch (rows 2h, 2h+1; cols 4*wp..4*wp+3)
    const float* xin = x + (size_t)bc * (HI * WI) + (size_t)(2 * h) * WI + 4 * wp;

    // Front-batch both 16B loads (MLP=2, fully coalesced across the warp)
    float4 r0 = *reinterpret_cast<const float4*>(xin);
    float4 r1 = *reinterpret_cast<const float4*>(xin + WI);

    float wa = __ldg(w_avg + c);
    float wm = __ldg(w_max + c);
    float ca = wa * wa * 0.25f;   // folds the /4 of avg-pool
    float cm = wm * wm;

    float sum0 = (r0.x + r0.y) + (r1.x + r1.y);
    float sum1 = (r0.z + r0.w) + (r1.z + r1.w);
    float mx0  = fmaxf(fmaxf(r0.x, r0.y), fmaxf(r1.x, r1.y));
    float mx1  = fmaxf(fmaxf(r0.z, r0.w), fmaxf(r1.z, r1.w));

    float2 o;
    o.x = fmaf(ca, sum0, cm * mx0);
    o.y = fmaf(ca, sum1, cm * mx1);

    *reinterpret_cast<float2*>(out + (size_t)bc * (HO * WO) + (size_t)h * WO + 2 * wp) = o;
}

extern "C" void kernel_launch(void* const* d_in, const int* in_sizes, int n_in,
                              void* d_out, int out_size)
{
    const float* x     = (const float*)d_in[0];
    const float* w_avg = (const float*)d_in[1];
    const float* w_max = (const float*)d_in[2];
    float* out = (float*)d_out;

    const int total  = B * C * HO * WP;           // 19,267,584
    const int threads = 256;
    const int blocks  = (total + threads - 1) / threads;  // 75,264 exactly

    comb_pool2d_kernel<<<blocks, threads>>>(x, w_avg, w_max, out);
}

// round 2
// speedup vs baseline: 1.0304x; 1.0304x over previous
#include <cuda_runtime.h>

// CombPool2d: out = (w_avg^2)*avg_pool2x2(x) + (w_max^2)*max_pool2x2(x)
// x: (16,192,224,224) fp32, out: (16,192,112,112) fp32. Pure HBM stream.
// 4 output pixels per thread: 4x float4 loads (MLP=4), 1x float4 store,
// streaming cache hints (data is touched exactly once).

#define B   16
#define C   192
#define HI  224
#define WI  224
#define HO  112
#define WO  112
#define WQ  (WO / 4)   // output quads per row = 28

__global__ __launch_bounds__(256)
void comb_pool2d_kernel(const float* __restrict__ x,
                        const float* __restrict__ w_avg,
                        const float* __restrict__ w_max,
                        float* __restrict__ out)
{
    const int total = B * C * HO * WQ;            // 9,633,792
    int tid = blockIdx.x * blockDim.x + threadIdx.x;
    if (tid >= total) return;

    int wq = tid % WQ;          // which quad of output columns
    int t  = tid / WQ;
    int h  = t % HO;            // output row
    int bc = t / HO;            // fused batch*channel index
    int c  = bc % C;

    // Input base: rows 2h, 2h+1; cols 8*wq .. 8*wq+7 (2x8 patch)
    const float4* xin = reinterpret_cast<const float4*>(
        x + (size_t)bc * (HI * WI) + (size_t)(2 * h) * WI + 8 * wq);

    // Front-batch all four 16B loads (MLP=4, fully coalesced, evict-first)
    float4 r0a = __ldcs(xin);
    float4 r0b = __ldcs(xin + 1);
    float4 r1a = __ldcs(xin + WI / 4);
    float4 r1b = __ldcs(xin + WI / 4 + 1);

    float wa = __ldg(w_avg + c);
    float wm = __ldg(w_max + c);
    float ca = wa * wa * 0.25f;   // folds the /4 of avg-pool
    float cm = wm * wm;

    float sum0 = (r0a.x + r0a.y) + (r1a.x + r1a.y);
    float sum1 = (r0a.z + r0a.w) + (r1a.z + r1a.w);
    float sum2 = (r0b.x + r0b.y) + (r1b.x + r1b.y);
    float sum3 = (r0b.z + r0b.w) + (r1b.z + r1b.w);

    float mx0 = fmaxf(fmaxf(r0a.x, r0a.y), fmaxf(r1a.x, r1a.y));
    float mx1 = fmaxf(fmaxf(r0a.z, r0a.w), fmaxf(r1a.z, r1a.w));
    float mx2 = fmaxf(fmaxf(r0b.x, r0b.y), fmaxf(r1b.x, r1b.y));
    float mx3 = fmaxf(fmaxf(r0b.z, r0b.w), fmaxf(r1b.z, r1b.w));

    float4 o;
    o.x = fmaf(ca, sum0, cm * mx0);
    o.y = fmaf(ca, sum1, cm * mx1);
    o.z = fmaf(ca, sum2, cm * mx2);
    o.w = fmaf(ca, sum3, cm * mx3);

    __stcs(reinterpret_cast<float4*>(
               out + (size_t)bc * (HO * WO) + (size_t)h * WO + 4 * wq), o);
}

extern "C" void kernel_launch(void* const* d_in, const int* in_sizes, int n_in,
                              void* d_out, int out_size)
{
    const float* x     = (const float*)d_in[0];
    const float* w_avg = (const float*)d_in[1];
    const float* w_max = (const float*)d_in[2];
    float* out = (float*)d_out;

    const int total   = B * C * HO * WQ;           // 9,633,792
    const int threads = 256;
    const int blocks  = (total + threads - 1) / threads;  // 37,632 exactly

    comb_pool2d_kernel<<<blocks, threads>>>(x, w_avg, w_max, out);
}